// round 8
// baseline (speedup 1.0000x reference)
#include <cuda_runtime.h>
#include <cuda_bf16.h>
#include <cstdint>

// ---------------------------------------------------------------------------
// Problem constants
// ---------------------------------------------------------------------------
#define BQ   16
#define HQ   64
#define WQ   64
#define DIMC 512
#define HIDD 1024
#define NPIX (BQ * HQ * WQ)          // 65536

// ---------------------------------------------------------------------------
// Scratch (device globals: allocation-free rule)
// ---------------------------------------------------------------------------
__device__ __align__(256) float          g_h1[(size_t)NPIX * DIMC];     // LN1 output
__device__ __align__(256) float          g_x1[(size_t)NPIX * DIMC];     // residual after block 1
__device__ __align__(256) __nv_bfloat16  g_xn[(size_t)NPIX * DIMC];     // l2norm(LN2(x1)) bf16
__device__ __align__(256) __nv_bfloat16  g_hidden[(size_t)NPIX * HIDD]; // gelu(sim*scale_in) bf16
__device__ __align__(256) __nv_bfloat16  g_win[(size_t)HIDD * DIMC];    // normalized proto_in^T  [n][k]
__device__ __align__(256) __nv_bfloat16  g_wout[(size_t)DIMC * HIDD];   // normalized proto_out^T [n][k]
__device__ float          g_gp[BQ * DIMC];               // per-(b,c) sum of LN1
__device__ float          g_rss[NPIX];                   // per-row sumsq of hidden

// ---------------------------------------------------------------------------
// PTX helpers (baseline compute_103-safe: cp.async, ldmatrix, mma.sync)
// ---------------------------------------------------------------------------
__device__ __forceinline__ uint32_t smem_to_u32(const void* p) {
    uint32_t a;
    asm("{ .reg .u64 t; cvta.to.shared.u64 t, %1; cvt.u32.u64 %0, t; }" : "=r"(a) : "l"(p));
    return a;
}

__device__ __forceinline__ void cp_async16(uint32_t saddr, const void* gaddr) {
    asm volatile("cp.async.cg.shared.global [%0], [%1], 16;" :: "r"(saddr), "l"(gaddr));
}
#define CP_COMMIT() asm volatile("cp.async.commit_group;" ::: "memory")
#define CP_WAIT(n)  asm volatile("cp.async.wait_group %0;" :: "n"(n) : "memory")

__device__ __forceinline__ void ldsm_x4(uint32_t* r, uint32_t addr) {
    asm volatile("ldmatrix.sync.aligned.m8n8.x4.shared.b16 {%0,%1,%2,%3}, [%4];"
                 : "=r"(r[0]), "=r"(r[1]), "=r"(r[2]), "=r"(r[3]) : "r"(addr));
}

__device__ __forceinline__ void mma_bf16(float* c, const uint32_t* a, const uint32_t* b) {
    asm volatile(
        "mma.sync.aligned.m16n8k16.row.col.f32.bf16.bf16.f32 "
        "{%0,%1,%2,%3}, {%4,%5,%6,%7}, {%8,%9}, {%0,%1,%2,%3};"
        : "+f"(c[0]), "+f"(c[1]), "+f"(c[2]), "+f"(c[3])
        : "r"(a[0]), "r"(a[1]), "r"(a[2]), "r"(a[3]), "r"(b[0]), "r"(b[1]));
}

// ---------------------------------------------------------------------------
// GEMM tiling constants
// ---------------------------------------------------------------------------
#define BK 32
#define PITCH 80                         // bytes per SMEM tile row (64B data + 16B pad)
#define TILE_BYTES (128 * PITCH)         // 10240 B
#define GEMM_SMEM_BYTES (6 * TILE_BYTES) // A(3 stages) + B(3 stages) = 61440 B

// ---------------------------------------------------------------------------
// Block reduce (256 threads): returns (sum a, sum b) broadcast
// ---------------------------------------------------------------------------
__device__ __forceinline__ float2 blk_reduce2(float a, float b) {
    __shared__ float sA[8], sB[8];
    unsigned lane = threadIdx.x & 31, wi = threadIdx.x >> 5;
    #pragma unroll
    for (int o = 16; o; o >>= 1) {
        a += __shfl_xor_sync(0xFFFFFFFFu, a, o);
        b += __shfl_xor_sync(0xFFFFFFFFu, b, o);
    }
    if (lane == 0) { sA[wi] = a; sB[wi] = b; }
    __syncthreads();
    if (wi == 0) {
        float ra = (lane < 8) ? sA[lane] : 0.f;
        float rb = (lane < 8) ? sB[lane] : 0.f;
        #pragma unroll
        for (int o = 4; o; o >>= 1) {
            ra += __shfl_xor_sync(0xFFFFFFFFu, ra, o);
            rb += __shfl_xor_sync(0xFFFFFFFFu, rb, o);
        }
        if (lane == 0) { sA[0] = ra; sB[0] = rb; }
    }
    __syncthreads();
    float2 r = make_float2(sA[0], sB[0]);
    __syncthreads();
    return r;
}

// ---------------------------------------------------------------------------
// K0: zero accumulators
// ---------------------------------------------------------------------------
__global__ void zero_kernel() {
    int i = blockIdx.x * blockDim.x + threadIdx.x;
    if (i < NPIX) g_rss[i] = 0.f;
    if (i < BQ * DIMC) g_gp[i] = 0.f;
}

// ---------------------------------------------------------------------------
// Weight prep: column-l2-normalize, transpose to [n][k], cast bf16
// ---------------------------------------------------------------------------
__global__ void __launch_bounds__(256) prep_win_kernel(const float* __restrict__ pin) {
    __shared__ float sred[256];
    int j = blockIdx.x;                       // output col 0..1023
    float s = 0.f;
    for (int i = threadIdx.x; i < DIMC; i += 256) {
        float v = pin[(size_t)i * HIDD + j];
        s += v * v;
    }
    sred[threadIdx.x] = s; __syncthreads();
    for (int o = 128; o; o >>= 1) {
        if (threadIdx.x < (unsigned)o) sred[threadIdx.x] += sred[threadIdx.x + o];
        __syncthreads();
    }
    float inv = 1.f / fmaxf(sqrtf(sred[0]), 1e-12f);
    for (int i = threadIdx.x; i < DIMC; i += 256)
        g_win[(size_t)j * DIMC + i] = __float2bfloat16(pin[(size_t)i * HIDD + j] * inv);
}

__global__ void __launch_bounds__(256) prep_wout_kernel(const float* __restrict__ pout) {
    __shared__ float sred[256];
    int j = blockIdx.x;                       // output col 0..511
    float s = 0.f;
    for (int i = threadIdx.x; i < HIDD; i += 256) {
        float v = pout[(size_t)i * DIMC + j];
        s += v * v;
    }
    sred[threadIdx.x] = s; __syncthreads();
    for (int o = 128; o; o >>= 1) {
        if (threadIdx.x < (unsigned)o) sred[threadIdx.x] += sred[threadIdx.x + o];
        __syncthreads();
    }
    float inv = 1.f / fmaxf(sqrtf(sred[0]), 1e-12f);
    for (int i = threadIdx.x; i < HIDD; i += 256)
        g_wout[(size_t)j * HIDD + i] = __float2bfloat16(pout[(size_t)i * DIMC + j] * inv);
}

// ---------------------------------------------------------------------------
// K1: LN1 + accumulate global-pool sums. One block per (b,h), loops over w.
// ---------------------------------------------------------------------------
__global__ void __launch_bounds__(256) ln1_kernel(const float* __restrict__ x,
                                                  const float* __restrict__ w1,
                                                  const float* __restrict__ b1) {
    int bh = blockIdx.x;
    int b = bh >> 6;
    int c0 = threadIdx.x * 2;
    float wv0 = w1[c0], wv1 = w1[c0 + 1];
    float bv0 = b1[c0], bv1 = b1[c0 + 1];
    float acc0 = 0.f, acc1 = 0.f;
    for (int w = 0; w < WQ; w++) {
        size_t base = ((size_t)bh * WQ + w) * DIMC;
        float2 v = *reinterpret_cast<const float2*>(x + base + c0);
        float2 s = blk_reduce2(v.x + v.y, v.x * v.x + v.y * v.y);
        float mean = s.x * (1.f / 512.f);
        float var  = s.y * (1.f / 512.f) - mean * mean;
        float rinv = rsqrtf(var + 1e-5f);
        float l0 = (v.x - mean) * rinv * wv0 + bv0;
        float l1 = (v.y - mean) * rinv * wv1 + bv1;
        *reinterpret_cast<float2*>(g_h1 + base + c0) = make_float2(l0, l1);
        acc0 += l0; acc1 += l1;
    }
    atomicAdd(&g_gp[b * DIMC + c0], acc0);
    atomicAdd(&g_gp[b * DIMC + c0 + 1], acc1);
}

// ---------------------------------------------------------------------------
// K2: spatial stencil + residual 1 + LN2 + row L2-norm -> xn (bf16), x1 (f32)
// ---------------------------------------------------------------------------
__global__ void __launch_bounds__(256) spatial_ln2_kernel(const float* __restrict__ x,
                                                          const float* __restrict__ alpha,
                                                          const float* __restrict__ gamma,
                                                          const float* __restrict__ w2,
                                                          const float* __restrict__ b2) {
    int bh = blockIdx.x;
    int b = bh >> 6;
    int h = bh & 63;
    int c0 = threadIdx.x * 2;
    float al0 = alpha[c0], al1 = alpha[c0 + 1];
    float gm0 = gamma[c0], gm1 = gamma[c0 + 1];
    float wv0 = w2[c0], wv1 = w2[c0 + 1];
    float bv0 = b2[c0], bv1 = b2[c0 + 1];
    float gp0 = g_gp[b * DIMC + c0]     * (1.f / 4096.f);
    float gp1 = g_gp[b * DIMC + c0 + 1] * (1.f / 4096.f);
    const float2 Z = make_float2(0.f, 0.f);
    for (int w = 0; w < WQ; w++) {
        size_t base = ((size_t)bh * WQ + w) * DIMC;
        float2 cc = *reinterpret_cast<const float2*>(g_h1 + base + c0);
        float2 up = (h > 0)  ? *reinterpret_cast<const float2*>(g_h1 + base - (size_t)WQ * DIMC + c0) : Z;
        float2 dn = (h < 63) ? *reinterpret_cast<const float2*>(g_h1 + base + (size_t)WQ * DIMC + c0) : Z;
        float2 lf = (w > 0)  ? *reinterpret_cast<const float2*>(g_h1 + base - DIMC + c0) : Z;
        float2 rt = (w < 63) ? *reinterpret_cast<const float2*>(g_h1 + base + DIMC + c0) : Z;
        float e0 = fabsf(cc.x - up.x) + fabsf(cc.x - dn.x) + fabsf(cc.x - lf.x) + fabsf(cc.x - rt.x);
        float e1 = fabsf(cc.y - up.y) + fabsf(cc.y - dn.y) + fabsf(cc.y - lf.y) + fabsf(cc.y - rt.y);
        float sp0 = e0 * al0 + gp0 * (1.f - al0);
        float sp1 = e1 * al1 + gp1 * (1.f - al1);
        float2 xv = *reinterpret_cast<const float2*>(x + base + c0);
        float x10 = xv.x + gm0 * sp0;
        float x11 = xv.y + gm1 * sp1;
        *reinterpret_cast<float2*>(g_x1 + base + c0) = make_float2(x10, x11);
        float2 s = blk_reduce2(x10 + x11, x10 * x10 + x11 * x11);
        float mean = s.x * (1.f / 512.f);
        float var  = s.y * (1.f / 512.f) - mean * mean;
        float rinv = rsqrtf(var + 1e-5f);
        float l0 = (x10 - mean) * rinv * wv0 + bv0;
        float l1 = (x11 - mean) * rinv * wv1 + bv1;
        float2 q = blk_reduce2(l0 * l0 + l1 * l1, 0.f);
        float inv = 1.f / fmaxf(sqrtf(q.x), 1e-12f);
        *reinterpret_cast<__nv_bfloat162*>(g_xn + base + c0) =
            __floats2bfloat162_rn(l0 * inv, l1 * inv);
    }
}

// ---------------------------------------------------------------------------
// cp.async stage loader: A tile [m0..m0+128) x BK, B tile [n0..n0+128) x BK
// Both K-major bf16; 16B chunks; 2 chunks per thread per operand.
// ---------------------------------------------------------------------------
template <int KDIM>
__device__ __forceinline__ void issue_stage(const __nv_bfloat16* __restrict__ A,
                                            const __nv_bfloat16* __restrict__ B,
                                            int m0, int n0, int kc,
                                            uint32_t smem_u32, int s, int tid) {
    uint32_t sa = smem_u32 + s * TILE_BYTES;
    uint32_t sb = smem_u32 + 3 * TILE_BYTES + s * TILE_BYTES;
    #pragma unroll
    for (int i = 0; i < 2; i++) {
        int o = tid + i * 256;
        int r = o >> 2, c = o & 3;
        cp_async16(sa + r * PITCH + c * 16, A + (size_t)(m0 + r) * KDIM + kc * BK + c * 8);
        cp_async16(sb + r * PITCH + c * 16, B + (size_t)(n0 + r) * KDIM + kc * BK + c * 8);
    }
}

// ---------------------------------------------------------------------------
// Mainloop: C[128x128] = A[128xK] * B[128xK]^T, bf16 mma.sync, fp32 accum.
// 8 warps: 4 along M (32 rows each) x 2 along N (64 cols each).
// 3-stage cp.async pipeline, BK=32 (2 k16 steps / stage).
// ---------------------------------------------------------------------------
template <int KDIM>
__device__ __forceinline__ void gemm_tile(const __nv_bfloat16* __restrict__ A,
                                          const __nv_bfloat16* __restrict__ B,
                                          int m0, int n0, float c[2][8][4]) {
    extern __shared__ char smem[];
    const int tid  = threadIdx.x;
    const int lane = tid & 31;
    const int wid  = tid >> 5;
    const int mw   = wid >> 1;
    const int nw   = wid & 1;
    const uint32_t smem_u32 = smem_to_u32(smem);
    constexpr int NCH = KDIM / BK;

    #pragma unroll
    for (int mi = 0; mi < 2; mi++)
        #pragma unroll
        for (int ni = 0; ni < 8; ni++)
            #pragma unroll
            for (int q = 0; q < 4; q++) c[mi][ni][q] = 0.f;

    issue_stage<KDIM>(A, B, m0, n0, 0, smem_u32, 0, tid); CP_COMMIT();
    issue_stage<KDIM>(A, B, m0, n0, 1, smem_u32, 1, tid); CP_COMMIT();

    // ldmatrix lane byte-offsets within a tile (kstep adds +32B)
    uint32_t aoff[2];
    #pragma unroll
    for (int mi = 0; mi < 2; mi++)
        aoff[mi] = (uint32_t)(mw * 32 + mi * 16 + (lane & 15)) * PITCH + ((lane >> 4) & 1) * 16;
    uint32_t boff[4];
    #pragma unroll
    for (int ng = 0; ng < 4; ng++)
        boff[ng] = (uint32_t)(nw * 64 + ng * 16 + (lane & 7) + ((lane & 16) ? 8 : 0)) * PITCH
                 + ((lane >> 3) & 1) * 16;

    #pragma unroll 1
    for (int kc = 0; kc < NCH; kc++) {
        CP_WAIT(1);
        __syncthreads();
        if (kc + 2 < NCH)
            issue_stage<KDIM>(A, B, m0, n0, kc + 2, smem_u32, (kc + 2) % 3, tid);
        CP_COMMIT();

        uint32_t sa = smem_u32 + (kc % 3) * TILE_BYTES;
        uint32_t sb = smem_u32 + 3 * TILE_BYTES + (kc % 3) * TILE_BYTES;
        #pragma unroll
        for (int ks = 0; ks < 2; ks++) {
            uint32_t af[2][4];
            ldsm_x4(af[0], sa + aoff[0] + ks * 32);
            ldsm_x4(af[1], sa + aoff[1] + ks * 32);
            uint32_t bf[8][2];
            #pragma unroll
            for (int ng = 0; ng < 4; ng++) {
                uint32_t t4[4];
                ldsm_x4(t4, sb + boff[ng] + ks * 32);
                bf[ng * 2][0]     = t4[0]; bf[ng * 2][1]     = t4[1];
                bf[ng * 2 + 1][0] = t4[2]; bf[ng * 2 + 1][1] = t4[3];
            }
            #pragma unroll
            for (int mi = 0; mi < 2; mi++)
                #pragma unroll
                for (int ni = 0; ni < 8; ni++)
                    mma_bf16(c[mi][ni], af[mi], bf[ni]);
        }
        __syncthreads();
    }
}

// ---------------------------------------------------------------------------
// GEMM1: sim = xn @ win^T; hidden = gelu(sim*scale_in) -> bf16; rowsumsq atomic
// ---------------------------------------------------------------------------
__global__ void __launch_bounds__(256) gemm1_kernel(const float* __restrict__ scale_in) {
    int n0 = blockIdx.x * 128;
    int m0 = blockIdx.y * 128;
    float c[2][8][4];
    gemm_tile<DIMC>(g_xn, g_win, m0, n0, c);

    const int lane = threadIdx.x & 31;
    const int wid  = threadIdx.x >> 5;
    const int mw   = wid >> 1;
    const int nw   = wid & 1;
    float sin_ = scale_in[0];

    #pragma unroll
    for (int mi = 0; mi < 2; mi++) {
        int r0 = m0 + mw * 32 + mi * 16 + (lane >> 2);
        float s0 = 0.f, s1 = 0.f;
        #pragma unroll
        for (int ni = 0; ni < 8; ni++) {
            int col = n0 + nw * 64 + ni * 8 + (lane & 3) * 2;
            float v0 = c[mi][ni][0] * sin_, v1 = c[mi][ni][1] * sin_;
            float v2 = c[mi][ni][2] * sin_, v3 = c[mi][ni][3] * sin_;
            float h0 = v0 * normcdff(v0), h1 = v1 * normcdff(v1);
            float h2 = v2 * normcdff(v2), h3 = v3 * normcdff(v3);
            s0 += h0 * h0 + h1 * h1;
            s1 += h2 * h2 + h3 * h3;
            *reinterpret_cast<__nv_bfloat162*>(&g_hidden[(size_t)r0 * HIDD + col]) =
                __floats2bfloat162_rn(h0, h1);
            *reinterpret_cast<__nv_bfloat162*>(&g_hidden[(size_t)(r0 + 8) * HIDD + col]) =
                __floats2bfloat162_rn(h2, h3);
        }
        atomicAdd(&g_rss[r0], s0);
        atomicAdd(&g_rss[r0 + 8], s1);
    }
}

// ---------------------------------------------------------------------------
// GEMM2: out = x1 + gamma * (hn @ wout^T * scale_out), hn = hidden / rownorm
// ---------------------------------------------------------------------------
__global__ void __launch_bounds__(256) gemm2_kernel(const float* __restrict__ scale_out,
                                                    const float* __restrict__ gamma,
                                                    float* __restrict__ out) {
    int n0 = blockIdx.x * 128;
    int m0 = blockIdx.y * 128;
    float c[2][8][4];
    gemm_tile<HIDD>(g_hidden, g_wout, m0, n0, c);

    const int lane = threadIdx.x & 31;
    const int wid  = threadIdx.x >> 5;
    const int mw   = wid >> 1;
    const int nw   = wid & 1;
    float so = scale_out[0];

    #pragma unroll
    for (int mi = 0; mi < 2; mi++) {
        int r0 = m0 + mw * 32 + mi * 16 + (lane >> 2);
        float fac0 = so / fmaxf(sqrtf(g_rss[r0]),     1e-12f);
        float fac1 = so / fmaxf(sqrtf(g_rss[r0 + 8]), 1e-12f);
        #pragma unroll
        for (int ni = 0; ni < 8; ni++) {
            int col = n0 + nw * 64 + ni * 8 + (lane & 3) * 2;
            float2 gm = *reinterpret_cast<const float2*>(gamma + col);
            size_t ba = (size_t)r0 * DIMC + col;
            size_t bb = (size_t)(r0 + 8) * DIMC + col;
            float2 xa = *reinterpret_cast<const float2*>(g_x1 + ba);
            float2 xb = *reinterpret_cast<const float2*>(g_x1 + bb);
            float2 oa = make_float2(xa.x + gm.x * (c[mi][ni][0] * fac0),
                                    xa.y + gm.y * (c[mi][ni][1] * fac0));
            float2 ob = make_float2(xb.x + gm.x * (c[mi][ni][2] * fac1),
                                    xb.y + gm.y * (c[mi][ni][3] * fac1));
            *reinterpret_cast<float2*>(out + ba) = oa;
            *reinterpret_cast<float2*>(out + bb) = ob;
        }
    }
}

// ---------------------------------------------------------------------------
// Launch
// ---------------------------------------------------------------------------
extern "C" void kernel_launch(void* const* d_in, const int* in_sizes, int n_in,
                              void* d_out, int out_size) {
    (void)in_sizes; (void)n_in; (void)out_size;
    const float* x     = (const float*)d_in[0];
    const float* n1w   = (const float*)d_in[1];
    const float* n1b   = (const float*)d_in[2];
    const float* alpha = (const float*)d_in[3];
    const float* n2w   = (const float*)d_in[4];
    const float* n2b   = (const float*)d_in[5];
    const float* pin   = (const float*)d_in[6];
    const float* pout  = (const float*)d_in[7];
    const float* sin_  = (const float*)d_in[8];
    const float* sout_ = (const float*)d_in[9];
    const float* gamma = (const float*)d_in[10];
    float* out = (float*)d_out;

    cudaFuncSetAttribute(gemm1_kernel, cudaFuncAttributeMaxDynamicSharedMemorySize, GEMM_SMEM_BYTES);
    cudaFuncSetAttribute(gemm2_kernel, cudaFuncAttributeMaxDynamicSharedMemorySize, GEMM_SMEM_BYTES);

    zero_kernel<<<256, 256>>>();
    prep_win_kernel<<<HIDD, 256>>>(pin);
    prep_wout_kernel<<<DIMC, 256>>>(pout);
    ln1_kernel<<<BQ * HQ, 256>>>(x, n1w, n1b);
    spatial_ln2_kernel<<<BQ * HQ, 256>>>(x, alpha, gamma, n2w, n2b);
    gemm1_kernel<<<dim3(HIDD / 128, NPIX / 128), 256, GEMM_SMEM_BYTES>>>(sin_);
    gemm2_kernel<<<dim3(DIMC / 128, NPIX / 128), 256, GEMM_SMEM_BYTES>>>(sout_, gamma, out);
}